// round 2
// baseline (speedup 1.0000x reference)
#include <cuda_runtime.h>

// Problem constants
#define B_ 4
#define N_ 2048
#define C_ 1024
#define H_ 16
#define D_ 64

// Scratch (allocation-free rule: __device__ globals)
__device__ float g_q[B_ * H_ * N_ * D_];     // 32 MB  [B,H,N,D]
__device__ float g_k[B_ * H_ * N_ * D_];     // 32 MB
__device__ float g_v[B_ * H_ * N_ * D_];     // 32 MB
__device__ float g_attn[B_ * N_ * C_];       // 32 MB  [B,N,C] (heads merged)

// ---------------------------------------------------------------------------
// Kernel 1: qkv = x @ W_qkv^T scattered into g_q/g_k/g_v as [B,H,N,D].
// 128x128 tile, BK=8, double-buffered smem, 256 threads, 8x8 fragments.
// ---------------------------------------------------------------------------
__global__ __launch_bounds__(256) void qkv_gemm(const float* __restrict__ x,
                                                const float* __restrict__ W) {
    __shared__ float As[2][8][128];
    __shared__ float Bs[2][8][128];
    const int tid = threadIdx.x;
    const int tx = tid & 15, ty = tid >> 4;
    const int m0 = blockIdx.y * 128;
    const int n0 = blockIdx.x * 128;
    const int lrow = tid >> 1;            // 0..127
    const int kseg = (tid & 1) << 2;      // 0 or 4
    const float* pA = x + (size_t)(m0 + lrow) * C_ + kseg;
    const float* pB = W + (size_t)(n0 + lrow) * C_ + kseg;

    float acc[8][8] = {};

    // prologue: fill buffer 0
    {
        float4 av = *(const float4*)pA;
        float4 bv = *(const float4*)pB;
        As[0][kseg + 0][lrow] = av.x; As[0][kseg + 1][lrow] = av.y;
        As[0][kseg + 2][lrow] = av.z; As[0][kseg + 3][lrow] = av.w;
        Bs[0][kseg + 0][lrow] = bv.x; Bs[0][kseg + 1][lrow] = bv.y;
        Bs[0][kseg + 2][lrow] = bv.z; Bs[0][kseg + 3][lrow] = bv.w;
    }
    __syncthreads();

    int buf = 0;
    for (int k0 = 0; k0 < C_; k0 += 8) {
        const bool more = (k0 + 8 < C_);
        float4 na, nb;
        if (more) {
            na = *(const float4*)(pA + k0 + 8);
            nb = *(const float4*)(pB + k0 + 8);
        }
#pragma unroll
        for (int k = 0; k < 8; ++k) {
            float4 a0 = *(const float4*)&As[buf][k][ty << 2];
            float4 a1 = *(const float4*)&As[buf][k][(ty << 2) + 64];
            float4 b0 = *(const float4*)&Bs[buf][k][tx << 2];
            float4 b1 = *(const float4*)&Bs[buf][k][(tx << 2) + 64];
            float ar[8] = {a0.x, a0.y, a0.z, a0.w, a1.x, a1.y, a1.z, a1.w};
            float br[8] = {b0.x, b0.y, b0.z, b0.w, b1.x, b1.y, b1.z, b1.w};
#pragma unroll
            for (int i = 0; i < 8; ++i)
#pragma unroll
                for (int j = 0; j < 8; ++j)
                    acc[i][j] = fmaf(ar[i], br[j], acc[i][j]);
        }
        if (more) {
            const int nb_ = buf ^ 1;
            As[nb_][kseg + 0][lrow] = na.x; As[nb_][kseg + 1][lrow] = na.y;
            As[nb_][kseg + 2][lrow] = na.z; As[nb_][kseg + 3][lrow] = na.w;
            Bs[nb_][kseg + 0][lrow] = nb.x; Bs[nb_][kseg + 1][lrow] = nb.y;
            Bs[nb_][kseg + 2][lrow] = nb.z; Bs[nb_][kseg + 3][lrow] = nb.w;
            buf = nb_;
            __syncthreads();
        }
    }

    // Scatter epilogue: q/k/v select per 64-wide column group.
#pragma unroll
    for (int rg = 0; rg < 2; ++rg)
#pragma unroll
        for (int i = 0; i < 4; ++i) {
            const int m = m0 + (ty << 2) + rg * 64 + i;
            const int b = m >> 11;           // m / 2048
            const int nr = m & 2047;
#pragma unroll
            for (int cg = 0; cg < 2; ++cg) {
                const int n = n0 + cg * 64 + (tx << 2);
                const int t = n >> 10;       // 0=q,1=k,2=v
                const int h = (n >> 6) & 15;
                float* dst = (t == 0) ? g_q : (t == 1) ? g_k : g_v;
                float4 o = make_float4(acc[rg * 4 + i][cg * 4 + 0],
                                       acc[rg * 4 + i][cg * 4 + 1],
                                       acc[rg * 4 + i][cg * 4 + 2],
                                       acc[rg * 4 + i][cg * 4 + 3]);
                *(float4*)&dst[(size_t)(((b * H_ + h) * N_ + nr)) * D_ + (n & 63)] = o;
            }
        }
}

// ---------------------------------------------------------------------------
// Kernel 2: flash attention. One block per (bh, 64-row q tile), KV tile 64.
// 256 threads; 4x4 S fragment, 4x4 O fragment, register online-softmax with
// 16-lane shfl_xor reductions. Dynamic smem (~68 KB).
// ---------------------------------------------------------------------------
#define QT(d, r) sm[(d) * 68 + (r)]
#define KT(d, c) sm[64 * 68 + (d) * 68 + (c)]
#define VS(c, d) sm[2 * 64 * 68 + (c) * 68 + (d)]
#define SS(r, c) sm[3 * 64 * 68 + (r) * 68 + (c)]

__global__ __launch_bounds__(256) void attn_kernel() {
    extern __shared__ float sm[];
    const int tid = threadIdx.x;
    const int tx = tid & 15, ty = tid >> 4;
    const int q0 = blockIdx.x * 64;
    const int bh = blockIdx.y;
    const float* qp = g_q + (size_t)bh * N_ * D_;
    const float* kp = g_k + (size_t)bh * N_ * D_;
    const float* vp = g_v + (size_t)bh * N_ * D_;

    // Load Q tile transposed (once per block)
#pragma unroll
    for (int i = 0; i < 4; ++i) {
        int idx = tid + i * 256;
        int r = idx >> 4;
        int ds = (idx & 15) << 2;
        float4 v = *(const float4*)&qp[(size_t)(q0 + r) * D_ + ds];
        QT(ds + 0, r) = v.x; QT(ds + 1, r) = v.y;
        QT(ds + 2, r) = v.z; QT(ds + 3, r) = v.w;
    }

    float acc[4][4] = {};
    float mrow[4] = {-1e30f, -1e30f, -1e30f, -1e30f};
    float lrow[4] = {};
    const float scale = 0.125f;          // D^-0.5, D=64

    for (int c0 = 0; c0 < N_; c0 += 64) {
        __syncthreads();   // protect KT/VS/SS reuse (orders QT on iter 0)

        // Load K tile transposed + V tile
#pragma unroll
        for (int i = 0; i < 4; ++i) {
            int idx = tid + i * 256;
            int c = idx >> 4;
            int ds = (idx & 15) << 2;
            float4 kv = *(const float4*)&kp[(size_t)(c0 + c) * D_ + ds];
            KT(ds + 0, c) = kv.x; KT(ds + 1, c) = kv.y;
            KT(ds + 2, c) = kv.z; KT(ds + 3, c) = kv.w;
            float4 vv = *(const float4*)&vp[(size_t)(c0 + c) * D_ + ds];
            *(float4*)&VS(c, ds) = vv;
        }
        __syncthreads();

        // S = scale * (Q @ K^T): 4 rows x 4 cols per thread
        float s[4][4] = {};
#pragma unroll 8
        for (int d = 0; d < 64; ++d) {
            float4 a = *(const float4*)&QT(d, ty << 2);
            float4 b = *(const float4*)&KT(d, tx << 2);
            float ar[4] = {a.x, a.y, a.z, a.w};
            float br[4] = {b.x, b.y, b.z, b.w};
#pragma unroll
            for (int i = 0; i < 4; ++i)
#pragma unroll
                for (int j = 0; j < 4; ++j)
                    s[i][j] = fmaf(ar[i], br[j], s[i][j]);
        }

        // Register online-softmax; rows owned by 16-lane tx groups.
#pragma unroll
        for (int i = 0; i < 4; ++i) {
#pragma unroll
            for (int j = 0; j < 4; ++j) s[i][j] *= scale;
            float mx = fmaxf(fmaxf(s[i][0], s[i][1]), fmaxf(s[i][2], s[i][3]));
            mx = fmaxf(mx, __shfl_xor_sync(0xffffffffu, mx, 1));
            mx = fmaxf(mx, __shfl_xor_sync(0xffffffffu, mx, 2));
            mx = fmaxf(mx, __shfl_xor_sync(0xffffffffu, mx, 4));
            mx = fmaxf(mx, __shfl_xor_sync(0xffffffffu, mx, 8));
            mx = fmaxf(mx, mrow[i]);
            float al = __expf(mrow[i] - mx);
            float sum = 0.0f;
#pragma unroll
            for (int j = 0; j < 4; ++j) {
                float p = __expf(s[i][j] - mx);
                s[i][j] = p;
                sum += p;
            }
            sum += __shfl_xor_sync(0xffffffffu, sum, 1);
            sum += __shfl_xor_sync(0xffffffffu, sum, 2);
            sum += __shfl_xor_sync(0xffffffffu, sum, 4);
            sum += __shfl_xor_sync(0xffffffffu, sum, 8);
            lrow[i] = lrow[i] * al + sum;
            mrow[i] = mx;
#pragma unroll
            for (int j = 0; j < 4; ++j) acc[i][j] *= al;
            // stash probs for the PV product
            *(float4*)&SS((ty << 2) + i, tx << 2) =
                make_float4(s[i][0], s[i][1], s[i][2], s[i][3]);
        }
        __syncthreads();

        // O += P @ V
#pragma unroll 8
        for (int c = 0; c < 64; ++c) {
            float p0 = SS((ty << 2) + 0, c);
            float p1 = SS((ty << 2) + 1, c);
            float p2 = SS((ty << 2) + 2, c);
            float p3 = SS((ty << 2) + 3, c);
            float4 b = *(const float4*)&VS(c, tx << 2);
            acc[0][0] = fmaf(p0, b.x, acc[0][0]); acc[0][1] = fmaf(p0, b.y, acc[0][1]);
            acc[0][2] = fmaf(p0, b.z, acc[0][2]); acc[0][3] = fmaf(p0, b.w, acc[0][3]);
            acc[1][0] = fmaf(p1, b.x, acc[1][0]); acc[1][1] = fmaf(p1, b.y, acc[1][1]);
            acc[1][2] = fmaf(p1, b.z, acc[1][2]); acc[1][3] = fmaf(p1, b.w, acc[1][3]);
            acc[2][0] = fmaf(p2, b.x, acc[2][0]); acc[2][1] = fmaf(p2, b.y, acc[2][1]);
            acc[2][2] = fmaf(p2, b.z, acc[2][2]); acc[2][3] = fmaf(p2, b.w, acc[2][3]);
            acc[3][0] = fmaf(p3, b.x, acc[3][0]); acc[3][1] = fmaf(p3, b.y, acc[3][1]);
            acc[3][2] = fmaf(p3, b.z, acc[3][2]); acc[3][3] = fmaf(p3, b.w, acc[3][3]);
        }
    }

    // Write O to g_attn[b][n][h*64 + d]; lrow replicated across tx group.
    const int b = bh >> 4, h = bh & 15;
#pragma unroll
    for (int i = 0; i < 4; ++i) {
        const int r = (ty << 2) + i;
        const float inv = 1.0f / lrow[i];
        float4 o = make_float4(acc[i][0] * inv, acc[i][1] * inv,
                               acc[i][2] * inv, acc[i][3] * inv);
        *(float4*)&g_attn[(size_t)(b * N_ + q0 + r) * C_ + (h << 6) + (tx << 2)] = o;
    }
}

// ---------------------------------------------------------------------------
// Kernel 3: out = g_attn @ W_proj^T + b_proj  (same 128x128 GEMM)
// ---------------------------------------------------------------------------
__global__ __launch_bounds__(256) void proj_gemm(const float* __restrict__ W,
                                                 const float* __restrict__ bias,
                                                 float* __restrict__ out) {
    __shared__ float As[2][8][128];
    __shared__ float Bs[2][8][128];
    const int tid = threadIdx.x;
    const int tx = tid & 15, ty = tid >> 4;
    const int m0 = blockIdx.y * 128;
    const int n0 = blockIdx.x * 128;
    const int lrow = tid >> 1;
    const int kseg = (tid & 1) << 2;
    const float* pA = g_attn + (size_t)(m0 + lrow) * C_ + kseg;
    const float* pB = W + (size_t)(n0 + lrow) * C_ + kseg;

    float acc[8][8] = {};

    {
        float4 av = *(const float4*)pA;
        float4 bv = *(const float4*)pB;
        As[0][kseg + 0][lrow] = av.x; As[0][kseg + 1][lrow] = av.y;
        As[0][kseg + 2][lrow] = av.z; As[0][kseg + 3][lrow] = av.w;
        Bs[0][kseg + 0][lrow] = bv.x; Bs[0][kseg + 1][lrow] = bv.y;
        Bs[0][kseg + 2][lrow] = bv.z; Bs[0][kseg + 3][lrow] = bv.w;
    }
    __syncthreads();

    int buf = 0;
    for (int k0 = 0; k0 < C_; k0 += 8) {
        const bool more = (k0 + 8 < C_);
        float4 na, nb;
        if (more) {
            na = *(const float4*)(pA + k0 + 8);
            nb = *(const float4*)(pB + k0 + 8);
        }
#pragma unroll
        for (int k = 0; k < 8; ++k) {
            float4 a0 = *(const float4*)&As[buf][k][ty << 2];
            float4 a1 = *(const float4*)&As[buf][k][(ty << 2) + 64];
            float4 b0 = *(const float4*)&Bs[buf][k][tx << 2];
            float4 b1 = *(const float4*)&Bs[buf][k][(tx << 2) + 64];
            float ar[8] = {a0.x, a0.y, a0.z, a0.w, a1.x, a1.y, a1.z, a1.w};
            float br[8] = {b0.x, b0.y, b0.z, b0.w, b1.x, b1.y, b1.z, b1.w};
#pragma unroll
            for (int i = 0; i < 8; ++i)
#pragma unroll
                for (int j = 0; j < 8; ++j)
                    acc[i][j] = fmaf(ar[i], br[j], acc[i][j]);
        }
        if (more) {
            const int nb_ = buf ^ 1;
            As[nb_][kseg + 0][lrow] = na.x; As[nb_][kseg + 1][lrow] = na.y;
            As[nb_][kseg + 2][lrow] = na.z; As[nb_][kseg + 3][lrow] = na.w;
            Bs[nb_][kseg + 0][lrow] = nb.x; Bs[nb_][kseg + 1][lrow] = nb.y;
            Bs[nb_][kseg + 2][lrow] = nb.z; Bs[nb_][kseg + 3][lrow] = nb.w;
            buf = nb_;
            __syncthreads();
        }
    }

#pragma unroll
    for (int cg = 0; cg < 2; ++cg) {
        const int n = n0 + cg * 64 + (tx << 2);
        float4 bv = *(const float4*)&bias[n];
#pragma unroll
        for (int rg = 0; rg < 2; ++rg)
#pragma unroll
            for (int i = 0; i < 4; ++i) {
                const int m = m0 + (ty << 2) + rg * 64 + i;
                float4 o = make_float4(acc[rg * 4 + i][cg * 4 + 0] + bv.x,
                                       acc[rg * 4 + i][cg * 4 + 1] + bv.y,
                                       acc[rg * 4 + i][cg * 4 + 2] + bv.z,
                                       acc[rg * 4 + i][cg * 4 + 3] + bv.w);
                *(float4*)&out[(size_t)m * C_ + n] = o;
            }
    }
}

// ---------------------------------------------------------------------------
extern "C" void kernel_launch(void* const* d_in, const int* in_sizes, int n_in,
                              void* d_out, int out_size) {
    const float* x     = (const float*)d_in[0];   // [4,2048,1024]
    const float* Wqkv  = (const float*)d_in[1];   // [3072,1024]
    const float* Wproj = (const float*)d_in[2];   // [1024,1024]
    const float* bproj = (const float*)d_in[3];   // [1024]
    float* out = (float*)d_out;                   // [4,2048,1024]

    // attention kernel needs ~68 KB dynamic smem
    static const int ATTN_SMEM = 4 * 64 * 68 * (int)sizeof(float);  // 69632
    cudaFuncSetAttribute(attn_kernel,
                         cudaFuncAttributeMaxDynamicSharedMemorySize, ATTN_SMEM);

    // 1) QKV projection: [8192,1024] x [3072,1024]^T -> q,k,v [B,H,N,D]
    qkv_gemm<<<dim3(3 * C_ / 128, (B_ * N_) / 128), 256>>>(x, Wqkv);
    // 2) Attention per (b,h), 64-row q tiles, 64-wide KV tiles
    attn_kernel<<<dim3(N_ / 64, B_ * H_), 256, ATTN_SMEM>>>();
    // 3) Output projection + bias
    proj_gemm<<<dim3(C_ / 128, (B_ * N_) / 128), 256>>>(Wproj, bproj, out);
}

// round 15
// speedup vs baseline: 1.8004x; 1.8004x over previous
#include <cuda_runtime.h>
#include <cuda_bf16.h>
#include <cstdint>

// Problem constants
#define B_ 4
#define N_ 2048
#define C_ 1024
#define H_ 16
#define D_ 64

// split-bf16 (hi/lo) buffers
__device__ __nv_bfloat16 g_xh[B_ * N_ * C_], g_xl[B_ * N_ * C_];
__device__ __nv_bfloat16 g_wqh[3 * C_ * C_], g_wql[3 * C_ * C_];
__device__ __nv_bfloat16 g_wph[C_ * C_], g_wpl[C_ * C_];
__device__ __nv_bfloat16 g_qh[B_ * H_ * N_ * D_], g_ql[B_ * H_ * N_ * D_];  // [B,H,N,D]
__device__ __nv_bfloat16 g_kh[B_ * H_ * N_ * D_], g_kl[B_ * H_ * N_ * D_];  // [B,H,N,D]
__device__ __nv_bfloat16 g_vh[B_ * H_ * N_ * D_], g_vl[B_ * H_ * N_ * D_];  // [B,H,D,N] (!)
__device__ __nv_bfloat16 g_ah[B_ * N_ * C_], g_al[B_ * N_ * C_];            // [B,N,C]

// ===========================================================================
// helpers
// ===========================================================================
__device__ __forceinline__ uint32_t smem_to_u32(const void* p) {
    uint32_t a;
    asm("{ .reg .u64 t; cvta.to.shared.u64 t, %1; cvt.u32.u64 %0, t; }"
        : "=r"(a) : "l"(p));
    return a;
}
__device__ __forceinline__ uint32_t bf2u(__nv_bfloat162 v) {
    return *reinterpret_cast<uint32_t*>(&v);
}
// split two floats -> (hi bf16x2, lo bf16x2)
__device__ __forceinline__ void split2(float x, float y, uint32_t& hi, uint32_t& lo) {
    __nv_bfloat162 h = __floats2bfloat162_rn(x, y);
    __nv_bfloat162 l = __floats2bfloat162_rn(x - __bfloat162float(h.x),
                                             y - __bfloat162float(h.y));
    hi = bf2u(h);
    lo = bf2u(l);
}

// mma.sync m16n8k16 bf16 (sm_80+; compiles on plain compute_103)
__device__ __forceinline__ void mma16816(float* d, const uint32_t* a, const uint32_t* b) {
    asm volatile(
        "mma.sync.aligned.m16n8k16.row.col.f32.bf16.bf16.f32 "
        "{%0,%1,%2,%3},{%4,%5,%6,%7},{%8,%9},{%0,%1,%2,%3};"
        : "+f"(d[0]), "+f"(d[1]), "+f"(d[2]), "+f"(d[3])
        : "r"(a[0]), "r"(a[1]), "r"(a[2]), "r"(a[3]), "r"(b[0]), "r"(b[1]));
}
__device__ __forceinline__ void ldsm_x4(uint32_t* r, uint32_t addr) {
    asm volatile("ldmatrix.sync.aligned.m8n8.x4.shared.b16 {%0,%1,%2,%3}, [%4];"
                 : "=r"(r[0]), "=r"(r[1]), "=r"(r[2]), "=r"(r[3]) : "r"(addr));
}
__device__ __forceinline__ void ldsm_x2(uint32_t* r, uint32_t addr) {
    asm volatile("ldmatrix.sync.aligned.m8n8.x2.shared.b16 {%0,%1}, [%2];"
                 : "=r"(r[0]), "=r"(r[1]) : "r"(addr));
}

// ===========================================================================
// split kernels: fp32 -> bf16 hi + lo (destinations are __device__ symbols;
// kernel_launch contains launches only -> graph-safe)
// ===========================================================================
__device__ __forceinline__ void split_store(const float* __restrict__ s,
                                            __nv_bfloat16* hi, __nv_bfloat16* lo,
                                            int i) {
    float4 v = ((const float4*)s)[i];
    uint32_t h0, l0, h1, l1;
    split2(v.x, v.y, h0, l0);
    split2(v.z, v.w, h1, l1);
    ((uint2*)hi)[i] = make_uint2(h0, h1);
    ((uint2*)lo)[i] = make_uint2(l0, l1);
}
__global__ __launch_bounds__(256) void split_x(const float* __restrict__ s) {
    int i = blockIdx.x * blockDim.x + threadIdx.x;
    if (i < B_ * N_ * C_ / 4) split_store(s, g_xh, g_xl, i);
}
__global__ __launch_bounds__(256) void split_wq(const float* __restrict__ s) {
    int i = blockIdx.x * blockDim.x + threadIdx.x;
    if (i < 3 * C_ * C_ / 4) split_store(s, g_wqh, g_wql, i);
}
__global__ __launch_bounds__(256) void split_wp(const float* __restrict__ s) {
    int i = blockIdx.x * blockDim.x + threadIdx.x;
    if (i < C_ * C_ / 4) split_store(s, g_wph, g_wpl, i);
}

// ===========================================================================
// mma.sync GEMM mainloop: C[128x128] = A[128xK] * B[128xK]^T, K=1024.
// 512 thr = 16 warps 4(m) x 4(n), warp tile 32x32.
// Smem: 2 stages x 4 tiles(Ah,Al,Bh,Bl) x [128 rows x 128B]; swizzle ch^(row&7).
// ===========================================================================
#define TILE_BYTES 16384
#define STAGE_BYTES (4 * TILE_BYTES)
#define GEMM_SMEM (2 * STAGE_BYTES)   // 131072

__device__ __forceinline__ void gemm_mainloop(const __nv_bfloat16* __restrict__ Ah,
                                              const __nv_bfloat16* __restrict__ Al,
                                              const __nv_bfloat16* __restrict__ Bh,
                                              const __nv_bfloat16* __restrict__ Bl,
                                              int m0, int n0, char* smem,
                                              float acc[2][4][4]) {
    const int tid = threadIdx.x;
    const int lane = tid & 31;
    const int wid = tid >> 5;
    const int wm = wid & 3, wn = wid >> 2;

    const int grow = tid >> 2;
    const int gc = (tid & 3) << 1;
    const uint4* pAh = (const uint4*)(Ah + (size_t)(m0 + grow) * C_) + gc;
    const uint4* pAl = (const uint4*)(Al + (size_t)(m0 + grow) * C_) + gc;
    const uint4* pBh = (const uint4*)(Bh + (size_t)(n0 + grow) * C_) + gc;
    const uint4* pBl = (const uint4*)(Bl + (size_t)(n0 + grow) * C_) + gc;
    const uint32_t so0 = (uint32_t)(grow * 128 + (((gc + 0) ^ (grow & 7)) << 4));
    const uint32_t so1 = (uint32_t)(grow * 128 + (((gc + 1) ^ (grow & 7)) << 4));
    const uint32_t smem_u32 = smem_to_u32(smem);

    uint4 rg[8];
    rg[0] = pAh[0]; rg[1] = pAh[1]; rg[2] = pAl[0]; rg[3] = pAl[1];
    rg[4] = pBh[0]; rg[5] = pBh[1]; rg[6] = pBl[0]; rg[7] = pBl[1];
    {
        char* st = smem;
        *(uint4*)(st + 0 * TILE_BYTES + so0) = rg[0];
        *(uint4*)(st + 0 * TILE_BYTES + so1) = rg[1];
        *(uint4*)(st + 1 * TILE_BYTES + so0) = rg[2];
        *(uint4*)(st + 1 * TILE_BYTES + so1) = rg[3];
        *(uint4*)(st + 2 * TILE_BYTES + so0) = rg[4];
        *(uint4*)(st + 2 * TILE_BYTES + so1) = rg[5];
        *(uint4*)(st + 3 * TILE_BYTES + so0) = rg[6];
        *(uint4*)(st + 3 * TILE_BYTES + so1) = rg[7];
    }
    __syncthreads();

    for (int it = 0; it < 16; ++it) {
        const bool more = (it + 1) < 16;
        if (more) {
            const int o = (it + 1) * 8;
            rg[0] = pAh[o]; rg[1] = pAh[o + 1];
            rg[2] = pAl[o]; rg[3] = pAl[o + 1];
            rg[4] = pBh[o]; rg[5] = pBh[o + 1];
            rg[6] = pBl[o]; rg[7] = pBl[o + 1];
        }
        const uint32_t sb = smem_u32 + (it & 1) * STAGE_BYTES;
#pragma unroll
        for (int ks = 0; ks < 4; ++ks) {
            uint32_t ahf[2][4], alf[2][4];
#pragma unroll
            for (int mf = 0; mf < 2; ++mf) {
                const int row = wm * 32 + mf * 16 + (lane & 15);
                const int ch = ks * 2 + (lane >> 4);
                const uint32_t off = row * 128 + ((ch ^ (row & 7)) << 4);
                ldsm_x4(ahf[mf], sb + 0 * TILE_BYTES + off);
                ldsm_x4(alf[mf], sb + 1 * TILE_BYTES + off);
            }
#pragma unroll
            for (int nf = 0; nf < 4; ++nf) {
                const int row = wn * 32 + nf * 8 + (lane & 7);
                const int ch = ks * 2 + ((lane >> 3) & 1);
                const uint32_t off = row * 128 + ((ch ^ (row & 7)) << 4);
                uint32_t bhf[2], blf[2];
                ldsm_x2(bhf, sb + 2 * TILE_BYTES + off);
                ldsm_x2(blf, sb + 3 * TILE_BYTES + off);
#pragma unroll
                for (int mf = 0; mf < 2; ++mf) {
                    mma16816(acc[mf][nf], ahf[mf], bhf);
                    mma16816(acc[mf][nf], ahf[mf], blf);
                    mma16816(acc[mf][nf], alf[mf], bhf);
                }
            }
        }
        if (more) {
            char* st = smem + ((it + 1) & 1) * STAGE_BYTES;
            *(uint4*)(st + 0 * TILE_BYTES + so0) = rg[0];
            *(uint4*)(st + 0 * TILE_BYTES + so1) = rg[1];
            *(uint4*)(st + 1 * TILE_BYTES + so0) = rg[2];
            *(uint4*)(st + 1 * TILE_BYTES + so1) = rg[3];
            *(uint4*)(st + 2 * TILE_BYTES + so0) = rg[4];
            *(uint4*)(st + 2 * TILE_BYTES + so1) = rg[5];
            *(uint4*)(st + 3 * TILE_BYTES + so0) = rg[6];
            *(uint4*)(st + 3 * TILE_BYTES + so1) = rg[7];
            __syncthreads();
        }
    }
}

// ---------------------------------------------------------------------------
// Kernel 1: qkv = x @ W_qkv^T -> split-bf16 q/k ([B,H,N,D]) and v ([B,H,D,N])
// ---------------------------------------------------------------------------
__global__ __launch_bounds__(512) void qkv_gemm() {
    extern __shared__ char smem[];
    const int m0 = blockIdx.y * 128;
    const int n0 = blockIdx.x * 128;
    float acc[2][4][4] = {};
    gemm_mainloop(g_xh, g_xl, g_wqh, g_wql, m0, n0, smem, acc);

    const int tid = threadIdx.x;
    const int lane = tid & 31;
    const int wid = tid >> 5;
    const int wm = wid & 3, wn = wid >> 2;
    const int t = n0 >> 10;               // 0=q,1=k,2=v

#pragma unroll
    for (int mf = 0; mf < 2; ++mf) {
        const int row = m0 + wm * 32 + mf * 16 + (lane >> 2);
#pragma unroll
        for (int nf = 0; nf < 4; ++nf) {
            const int col = n0 + wn * 32 + nf * 8 + ((lane & 3) << 1);
            const int h = (col >> 6) & 15;
            const int d = col & 63;
#pragma unroll
            for (int rr = 0; rr < 2; ++rr) {
                const int m = row + rr * 8;
                const int b = m >> 11, nr = m & 2047;
                const float v0 = acc[mf][nf][rr * 2 + 0];
                const float v1 = acc[mf][nf][rr * 2 + 1];
                uint32_t hp, lp;
                split2(v0, v1, hp, lp);
                if (t == 2) {
                    // V transposed: [B,H,D,N]
                    const size_t base = ((size_t)(b * H_ + h) * D_ + d) * N_ + nr;
                    __nv_bfloat162 hv = *reinterpret_cast<__nv_bfloat162*>(&hp);
                    __nv_bfloat162 lv = *reinterpret_cast<__nv_bfloat162*>(&lp);
                    g_vh[base] = hv.x; g_vh[base + N_] = hv.y;
                    g_vl[base] = lv.x; g_vl[base + N_] = lv.y;
                } else {
                    const size_t base = ((size_t)(b * H_ + h) * N_ + nr) * D_ + d;
                    __nv_bfloat16* dh = (t == 0) ? g_qh : g_kh;
                    __nv_bfloat16* dl = (t == 0) ? g_ql : g_kl;
                    *(uint32_t*)&dh[base] = hp;
                    *(uint32_t*)&dl[base] = lp;
                }
            }
        }
    }
}

// ---------------------------------------------------------------------------
// Kernel 3: out = attn @ W_proj^T + b_proj
// ---------------------------------------------------------------------------
__global__ __launch_bounds__(512) void proj_gemm(const float* __restrict__ bias,
                                                 float* __restrict__ out) {
    extern __shared__ char smem[];
    const int m0 = blockIdx.y * 128;
    const int n0 = blockIdx.x * 128;
    float acc[2][4][4] = {};
    gemm_mainloop(g_ah, g_al, g_wph, g_wpl, m0, n0, smem, acc);

    const int tid = threadIdx.x;
    const int lane = tid & 31;
    const int wid = tid >> 5;
    const int wm = wid & 3, wn = wid >> 2;

#pragma unroll
    for (int mf = 0; mf < 2; ++mf) {
        const int row = m0 + wm * 32 + mf * 16 + (lane >> 2);
#pragma unroll
        for (int nf = 0; nf < 4; ++nf) {
            const int col = n0 + wn * 32 + nf * 8 + ((lane & 3) << 1);
            const float2 bv = *(const float2*)&bias[col];
            *(float2*)&out[(size_t)row * C_ + col] =
                make_float2(acc[mf][nf][0] + bv.x, acc[mf][nf][1] + bv.y);
            *(float2*)&out[(size_t)(row + 8) * C_ + col] =
                make_float2(acc[mf][nf][2] + bv.x, acc[mf][nf][3] + bv.y);
        }
    }
}

// ===========================================================================
// Kernel 2: flash attention via mma.sync split-bf16.
// One block per (bh, 128-row q tile); KV tiles of 64. 512 thr = 16 warps
// (4m x 4n). S-phase warp tile 32(m)x16(n); PV warp tile 32(m)x16(d).
// Softmax: one thread per q row on fp32 S in smem.
// ===========================================================================
#define AQH 0
#define AQL 16384
#define AKH 32768
#define AKL 40960
#define AVH 49152
#define AVL 57344
#define ASS 65536                 // [128][68] fp32 = 34816
#define APH 100352                // [128][128B]
#define APL 116736
#define AMS 133120                // 128 f32
#define ALS 133632
#define AAS 134144
#define ATTN_SMEM 134656

__global__ __launch_bounds__(512) void attn_mma() {
    extern __shared__ char sm[];
    const uint32_t sb = smem_to_u32(sm);
    const int tid = threadIdx.x;
    const int lane = tid & 31;
    const int wid = tid >> 5;
    const int wm = wid & 3, wn = wid >> 2;
    const int q0 = blockIdx.x * 128;
    const int bh = blockIdx.y;
    const int b = bh >> 4, h = bh & 15;

    const __nv_bfloat16* qh = g_qh + (size_t)bh * N_ * D_;
    const __nv_bfloat16* ql = g_ql + (size_t)bh * N_ * D_;
    const __nv_bfloat16* kh = g_kh + (size_t)bh * N_ * D_;
    const __nv_bfloat16* kl = g_kl + (size_t)bh * N_ * D_;
    const __nv_bfloat16* vh = g_vh + (size_t)bh * D_ * N_;   // [D][N]
    const __nv_bfloat16* vl = g_vl + (size_t)bh * D_ * N_;

    float* Ms = (float*)(sm + AMS);
    float* Ls = (float*)(sm + ALS);
    float* As = (float*)(sm + AAS);

    // Load Q tile (128 rows x 64 bf16 = 128B rows), hi+lo, swizzled.
    {
        const int grow = tid >> 2;            // 0..127
        const int gc = (tid & 3) << 1;        // chunks gc, gc+1 (of 8)
        const uint4* ph = (const uint4*)(qh + (size_t)(q0 + grow) * D_) + gc;
        const uint4* pl = (const uint4*)(ql + (size_t)(q0 + grow) * D_) + gc;
        const uint32_t so0 = grow * 128 + (((gc + 0) ^ (grow & 7)) << 4);
        const uint32_t so1 = grow * 128 + (((gc + 1) ^ (grow & 7)) << 4);
        *(uint4*)(sm + AQH + so0) = ph[0];
        *(uint4*)(sm + AQH + so1) = ph[1];
        *(uint4*)(sm + AQL + so0) = pl[0];
        *(uint4*)(sm + AQL + so1) = pl[1];
    }
    if (tid < 128) { Ms[tid] = -1e30f; Ls[tid] = 0.0f; }

    float acco[2][2][4] = {};

    for (int c0 = 0; c0 < N_; c0 += 64) {
        __syncthreads();   // protect K/V/S/P reuse; orders Q/Ms on iter 0

        // Load K tile [64][64] (rows kv) and Vt tile [64][64] (rows d)
        {
            const int half = tid >> 8;         // 0: K, 1: V
            const int t2 = tid & 255;
            const int trow = t2 >> 2;          // 0..63
            const int tch = (t2 & 3) << 1;
            const uint32_t so0 = trow * 128 + (((tch + 0) ^ (trow & 7)) << 4);
            const uint32_t so1 = trow * 128 + (((tch + 1) ^ (trow & 7)) << 4);
            if (half == 0) {
                const uint4* ph = (const uint4*)(kh + (size_t)(c0 + trow) * D_) + tch;
                const uint4* pl = (const uint4*)(kl + (size_t)(c0 + trow) * D_) + tch;
                *(uint4*)(sm + AKH + so0) = ph[0];
                *(uint4*)(sm + AKH + so1) = ph[1];
                *(uint4*)(sm + AKL + so0) = pl[0];
                *(uint4*)(sm + AKL + so1) = pl[1];
            } else {
                const uint4* ph = (const uint4*)(vh + (size_t)trow * N_ + c0) + tch;
                const uint4* pl = (const uint4*)(vl + (size_t)trow * N_ + c0) + tch;
                *(uint4*)(sm + AVH + so0) = ph[0];
                *(uint4*)(sm + AVH + so1) = ph[1];
                *(uint4*)(sm + AVL + so0) = pl[0];
                *(uint4*)(sm + AVL + so1) = pl[1];
            }
        }
        __syncthreads();

        // S = Q @ K^T  (warp tile 32m x 16n, k=64)
        float accs[2][2][4] = {};
#pragma unroll
        for (int ks = 0; ks < 4; ++ks) {
            uint32_t ahf[2][4], alf[2][4];
#pragma unroll
            for (int mf = 0; mf < 2; ++mf) {
                const int row = wm * 32 + mf * 16 + (lane & 15);
                const int ch = ks * 2 + (lane >> 4);
                const uint32_t off = row * 128 + ((ch ^ (row & 7)) << 4);
                ldsm_x4(ahf[mf], sb + AQH + off);
                ldsm_x4(alf[mf], sb + AQL + off);
            }
#pragma unroll
            for (int nf = 0; nf < 2; ++nf) {
                const int row = wn * 16 + nf * 8 + (lane & 7);
                const int ch = ks * 2 + ((lane >> 3) & 1);
                const uint32_t off = row * 128 + ((ch ^ (row & 7)) << 4);
                uint32_t bhf[2], blf[2];
                ldsm_x2(bhf, sb + AKH + off);
                ldsm_x2(blf, sb + AKL + off);
#pragma unroll
                for (int mf = 0; mf < 2; ++mf) {
                    mma16816(accs[mf][nf], ahf[mf], bhf);
                    mma16816(accs[mf][nf], ahf[mf], blf);
                    mma16816(accs[mf][nf], alf[mf], bhf);
                }
            }
        }
        // store S fragments to smem (fp32, [128][68])
#pragma unroll
        for (int mf = 0; mf < 2; ++mf) {
            const int r = wm * 32 + mf * 16 + (lane >> 2);
#pragma unroll
            for (int nf = 0; nf < 2; ++nf) {
                const int col = wn * 16 + nf * 8 + ((lane & 3) << 1);
                float* S = (float*)(sm + ASS);
                *(float2*)&S[r * 68 + col] = make_float2(accs[mf][nf][0], accs[mf][nf][1]);
                *(float2*)&S[(r + 8) * 68 + col] = make_float2(accs[mf][nf][2], accs[mf][nf][3]);
            }
        }
        __syncthreads();

        // online softmax, one thread per row; writes split-bf16 P
        if (tid < 128) {
            const int r = tid;
            float* Srow = (float*)(sm + ASS) + r * 68;
            float mx = Ms[r];
#pragma unroll 8
            for (int c = 0; c < 64; ++c) {
                float s = Srow[c] * 0.125f;
                Srow[c] = s;
                mx = fmaxf(mx, s);
            }
            const float al = __expf(Ms[r] - mx);
            float sum = 0.0f;
#pragma unroll 4
            for (int c = 0; c < 64; c += 2) {
                float p0 = __expf(Srow[c] - mx);
                float p1 = __expf(Srow[c + 1] - mx);
                sum += p0 + p1;
                uint32_t hp, lp;
                split2(p0, p1, hp, lp);
                const uint32_t off = r * 128 + (((c >> 3) ^ (r & 7)) << 4) + ((c * 2) & 15);
                *(uint32_t*)(sm + APH + off) = hp;
                *(uint32_t*)(sm + APL + off) = lp;
            }
            Ls[r] = Ls[r] * al + sum;
            Ms[r] = mx;
            As[r] = al;
        }
        __syncthreads();

        // rescale O by alpha, then O += P @ V
#pragma unroll
        for (int mf = 0; mf < 2; ++mf) {
            const int r = wm * 32 + mf * 16 + (lane >> 2);
            const float a1 = As[r], a2 = As[r + 8];
#pragma unroll
            for (int nf = 0; nf < 2; ++nf) {
                acco[mf][nf][0] *= a1; acco[mf][nf][1] *= a1;
                acco[mf][nf][2] *= a2; acco[mf][nf][3] *= a2;
            }
        }
#pragma unroll
        for (int ks = 0; ks < 4; ++ks) {
            uint32_t phf[2][4], plf[2][4];
#pragma unroll
            for (int mf = 0; mf < 2; ++mf) {
                const int row = wm * 32 + mf * 16 + (lane & 15);
                const int ch = ks * 2 + (lane >> 4);
                const uint32_t off = row * 128 + ((ch ^ (row & 7)) << 4);
                ldsm_x4(phf[mf], sb + APH + off);
                ldsm_x4(plf[mf], sb + APL + off);
            }
#pragma unroll
            for (int nf = 0; nf < 2; ++nf) {
                const int row = wn * 16 + nf * 8 + (lane & 7);   // d-row of Vt
                const int ch = ks * 2 + ((lane >> 3) & 1);
                const uint32_t off = row * 128 + ((ch ^ (row & 7)) << 4);
                uint32_t vhf[2], vlf[2];
                ldsm_x2(vhf, sb + AVH + off);
                ldsm_x2(vlf, sb + AVL + off);
#pragma unroll
                for (int mf = 0; mf < 2; ++mf) {
                    mma16816(acco[mf][nf], phf[mf], vhf);
                    mma16816(acco[mf][nf], phf[mf], vlf);
                    mma16816(acco[mf][nf], plf[mf], vhf);
                }
            }
        }
    }

    // epilogue: O / l -> split-bf16 g_ah/g_al at [b][token][h*64 + d]
#pragma unroll
    for (int mf = 0; mf < 2; ++mf) {
        const int r = wm * 32 + mf * 16 + (lane >> 2);
        const float inv1 = 1.0f / Ls[r];
        const float inv2 = 1.0f / Ls[r + 8];
#pragma unroll
        for (int nf = 0; nf < 2; ++nf) {
            const int d = wn * 16 + nf * 8 + ((lane & 3) << 1);
            uint32_t hp, lp;
            {
                const size_t base = (size_t)(b * N_ + q0 + r) * C_ + (h << 6) + d;
                split2(acco[mf][nf][0] * inv1, acco[mf][nf][1] * inv1, hp, lp);
                *(uint32_t*)&g_ah[base] = hp;
                *(uint32_t*)&g_al[base] = lp;
            }
            {
                const size_t base = (size_t)(b * N_ + q0 + r + 8) * C_ + (h << 6) + d;
                split2(acco[mf][nf][2] * inv2, acco[mf][nf][3] * inv2, hp, lp);
                *(uint32_t*)&g_ah[base] = hp;
                *(uint32_t*)&g_al[base] = lp;
            }
        }
    }
}

// ---------------------------------------------------------------------------
extern "C" void kernel_launch(void* const* d_in, const int* in_sizes, int n_in,
                              void* d_out, int out_size) {
    const float* x     = (const float*)d_in[0];   // [4,2048,1024]
    const float* Wqkv  = (const float*)d_in[1];   // [3072,1024]
    const float* Wproj = (const float*)d_in[2];   // [1024,1024]
    const float* bproj = (const float*)d_in[3];   // [1024]
    float* out = (float*)d_out;                   // [4,2048,1024]

    cudaFuncSetAttribute(qkv_gemm,
                         cudaFuncAttributeMaxDynamicSharedMemorySize, GEMM_SMEM);
    cudaFuncSetAttribute(proj_gemm,
                         cudaFuncAttributeMaxDynamicSharedMemorySize, GEMM_SMEM);
    cudaFuncSetAttribute(attn_mma,
                         cudaFuncAttributeMaxDynamicSharedMemorySize, ATTN_SMEM);

    // 0) split fp32 inputs into bf16 hi/lo (kernel launches only)
    split_x<<<(B_ * N_ * C_ / 4 + 255) / 256, 256>>>(x);
    split_wq<<<(3 * C_ * C_ / 4 + 255) / 256, 256>>>(Wqkv);
    split_wp<<<(C_ * C_ / 4 + 255) / 256, 256>>>(Wproj);
    // 1) QKV projection (mma.sync split-bf16) -> split q/k/v (v transposed)
    qkv_gemm<<<dim3(3 * C_ / 128, (B_ * N_) / 128), 512, GEMM_SMEM>>>();
    // 2) Attention (mma.sync split-bf16 flash attention)
    attn_mma<<<dim3(N_ / 128, B_ * H_), 512, ATTN_SMEM>>>();
    // 3) Output projection + bias (mma.sync split-bf16)
    proj_gemm<<<dim3(C_ / 128, (B_ * N_) / 128), 512, GEMM_SMEM>>>(bproj, out);
}

// round 16
// speedup vs baseline: 2.6769x; 1.4868x over previous
#include <cuda_runtime.h>
#include <cuda_bf16.h>
#include <cstdint>

// Problem constants
#define B_ 4
#define N_ 2048
#define C_ 1024
#define H_ 16
#define D_ 64

// split-bf16 (hi/lo) buffers
__device__ __nv_bfloat16 g_xh[B_ * N_ * C_], g_xl[B_ * N_ * C_];
__device__ __nv_bfloat16 g_wqh[3 * C_ * C_], g_wql[3 * C_ * C_];
__device__ __nv_bfloat16 g_wph[C_ * C_], g_wpl[C_ * C_];
__device__ __nv_bfloat16 g_qh[B_ * H_ * N_ * D_], g_ql[B_ * H_ * N_ * D_];  // [B,H,N,D]
__device__ __nv_bfloat16 g_kh[B_ * H_ * N_ * D_], g_kl[B_ * H_ * N_ * D_];  // [B,H,N,D]
__device__ __nv_bfloat16 g_vh[B_ * H_ * N_ * D_], g_vl[B_ * H_ * N_ * D_];  // [B,H,D,N] (!)
__device__ __nv_bfloat16 g_ah[B_ * N_ * C_], g_al[B_ * N_ * C_];            // [B,N,C]

// ===========================================================================
// helpers
// ===========================================================================
__device__ __forceinline__ uint32_t smem_to_u32(const void* p) {
    uint32_t a;
    asm("{ .reg .u64 t; cvta.to.shared.u64 t, %1; cvt.u32.u64 %0, t; }"
        : "=r"(a) : "l"(p));
    return a;
}
__device__ __forceinline__ uint32_t bf2u(__nv_bfloat162 v) {
    return *reinterpret_cast<uint32_t*>(&v);
}
// split two floats -> (hi bf16x2, lo bf16x2)
__device__ __forceinline__ void split2(float x, float y, uint32_t& hi, uint32_t& lo) {
    __nv_bfloat162 h = __floats2bfloat162_rn(x, y);
    __nv_bfloat162 l = __floats2bfloat162_rn(x - __bfloat162float(h.x),
                                             y - __bfloat162float(h.y));
    hi = bf2u(h);
    lo = bf2u(l);
}

// mma.sync m16n8k16 bf16 (HW-validated R15)
__device__ __forceinline__ void mma16816(float* d, const uint32_t* a, const uint32_t* b) {
    asm volatile(
        "mma.sync.aligned.m16n8k16.row.col.f32.bf16.bf16.f32 "
        "{%0,%1,%2,%3},{%4,%5,%6,%7},{%8,%9},{%0,%1,%2,%3};"
        : "+f"(d[0]), "+f"(d[1]), "+f"(d[2]), "+f"(d[3])
        : "r"(a[0]), "r"(a[1]), "r"(a[2]), "r"(a[3]), "r"(b[0]), "r"(b[1]));
}
__device__ __forceinline__ void ldsm_x4(uint32_t* r, uint32_t addr) {
    asm volatile("ldmatrix.sync.aligned.m8n8.x4.shared.b16 {%0,%1,%2,%3}, [%4];"
                 : "=r"(r[0]), "=r"(r[1]), "=r"(r[2]), "=r"(r[3]) : "r"(addr));
}
__device__ __forceinline__ void ldsm_x2(uint32_t* r, uint32_t addr) {
    asm volatile("ldmatrix.sync.aligned.m8n8.x2.shared.b16 {%0,%1}, [%2];"
                 : "=r"(r[0]), "=r"(r[1]) : "r"(addr));
}

// ===========================================================================
// split kernels: fp32 -> bf16 hi + lo
// ===========================================================================
__device__ __forceinline__ void split_store(const float* __restrict__ s,
                                            __nv_bfloat16* hi, __nv_bfloat16* lo,
                                            int i) {
    float4 v = ((const float4*)s)[i];
    uint32_t h0, l0, h1, l1;
    split2(v.x, v.y, h0, l0);
    split2(v.z, v.w, h1, l1);
    ((uint2*)hi)[i] = make_uint2(h0, h1);
    ((uint2*)lo)[i] = make_uint2(l0, l1);
}
__global__ __launch_bounds__(256) void split_x(const float* __restrict__ s) {
    int i = blockIdx.x * blockDim.x + threadIdx.x;
    if (i < B_ * N_ * C_ / 4) split_store(s, g_xh, g_xl, i);
}
__global__ __launch_bounds__(256) void split_wq(const float* __restrict__ s) {
    int i = blockIdx.x * blockDim.x + threadIdx.x;
    if (i < 3 * C_ * C_ / 4) split_store(s, g_wqh, g_wql, i);
}
__global__ __launch_bounds__(256) void split_wp(const float* __restrict__ s) {
    int i = blockIdx.x * blockDim.x + threadIdx.x;
    if (i < C_ * C_ / 4) split_store(s, g_wph, g_wpl, i);
}

// ===========================================================================
// mma.sync GEMM mainloop (unchanged, HW-validated): C[128x128], K=1024.
// ===========================================================================
#define TILE_BYTES 16384
#define STAGE_BYTES (4 * TILE_BYTES)
#define GEMM_SMEM (2 * STAGE_BYTES)   // 131072

__device__ __forceinline__ void gemm_mainloop(const __nv_bfloat16* __restrict__ Ah,
                                              const __nv_bfloat16* __restrict__ Al,
                                              const __nv_bfloat16* __restrict__ Bh,
                                              const __nv_bfloat16* __restrict__ Bl,
                                              int m0, int n0, char* smem,
                                              float acc[2][4][4]) {
    const int tid = threadIdx.x;
    const int lane = tid & 31;
    const int wid = tid >> 5;
    const int wm = wid & 3, wn = wid >> 2;

    const int grow = tid >> 2;
    const int gc = (tid & 3) << 1;
    const uint4* pAh = (const uint4*)(Ah + (size_t)(m0 + grow) * C_) + gc;
    const uint4* pAl = (const uint4*)(Al + (size_t)(m0 + grow) * C_) + gc;
    const uint4* pBh = (const uint4*)(Bh + (size_t)(n0 + grow) * C_) + gc;
    const uint4* pBl = (const uint4*)(Bl + (size_t)(n0 + grow) * C_) + gc;
    const uint32_t so0 = (uint32_t)(grow * 128 + (((gc + 0) ^ (grow & 7)) << 4));
    const uint32_t so1 = (uint32_t)(grow * 128 + (((gc + 1) ^ (grow & 7)) << 4));
    const uint32_t smem_u32 = smem_to_u32(smem);

    uint4 rg[8];
    rg[0] = pAh[0]; rg[1] = pAh[1]; rg[2] = pAl[0]; rg[3] = pAl[1];
    rg[4] = pBh[0]; rg[5] = pBh[1]; rg[6] = pBl[0]; rg[7] = pBl[1];
    {
        char* st = smem;
        *(uint4*)(st + 0 * TILE_BYTES + so0) = rg[0];
        *(uint4*)(st + 0 * TILE_BYTES + so1) = rg[1];
        *(uint4*)(st + 1 * TILE_BYTES + so0) = rg[2];
        *(uint4*)(st + 1 * TILE_BYTES + so1) = rg[3];
        *(uint4*)(st + 2 * TILE_BYTES + so0) = rg[4];
        *(uint4*)(st + 2 * TILE_BYTES + so1) = rg[5];
        *(uint4*)(st + 3 * TILE_BYTES + so0) = rg[6];
        *(uint4*)(st + 3 * TILE_BYTES + so1) = rg[7];
    }
    __syncthreads();

    for (int it = 0; it < 16; ++it) {
        const bool more = (it + 1) < 16;
        if (more) {
            const int o = (it + 1) * 8;
            rg[0] = pAh[o]; rg[1] = pAh[o + 1];
            rg[2] = pAl[o]; rg[3] = pAl[o + 1];
            rg[4] = pBh[o]; rg[5] = pBh[o + 1];
            rg[6] = pBl[o]; rg[7] = pBl[o + 1];
        }
        const uint32_t sb = smem_u32 + (it & 1) * STAGE_BYTES;
#pragma unroll
        for (int ks = 0; ks < 4; ++ks) {
            uint32_t ahf[2][4], alf[2][4];
#pragma unroll
            for (int mf = 0; mf < 2; ++mf) {
                const int row = wm * 32 + mf * 16 + (lane & 15);
                const int ch = ks * 2 + (lane >> 4);
                const uint32_t off = row * 128 + ((ch ^ (row & 7)) << 4);
                ldsm_x4(ahf[mf], sb + 0 * TILE_BYTES + off);
                ldsm_x4(alf[mf], sb + 1 * TILE_BYTES + off);
            }
#pragma unroll
            for (int nf = 0; nf < 4; ++nf) {
                const int row = wn * 32 + nf * 8 + (lane & 7);
                const int ch = ks * 2 + ((lane >> 3) & 1);
                const uint32_t off = row * 128 + ((ch ^ (row & 7)) << 4);
                uint32_t bhf[2], blf[2];
                ldsm_x2(bhf, sb + 2 * TILE_BYTES + off);
                ldsm_x2(blf, sb + 3 * TILE_BYTES + off);
#pragma unroll
                for (int mf = 0; mf < 2; ++mf) {
                    mma16816(acc[mf][nf], ahf[mf], bhf);
                    mma16816(acc[mf][nf], ahf[mf], blf);
                    mma16816(acc[mf][nf], alf[mf], bhf);
                }
            }
        }
        if (more) {
            char* st = smem + ((it + 1) & 1) * STAGE_BYTES;
            *(uint4*)(st + 0 * TILE_BYTES + so0) = rg[0];
            *(uint4*)(st + 0 * TILE_BYTES + so1) = rg[1];
            *(uint4*)(st + 1 * TILE_BYTES + so0) = rg[2];
            *(uint4*)(st + 1 * TILE_BYTES + so1) = rg[3];
            *(uint4*)(st + 2 * TILE_BYTES + so0) = rg[4];
            *(uint4*)(st + 2 * TILE_BYTES + so1) = rg[5];
            *(uint4*)(st + 3 * TILE_BYTES + so0) = rg[6];
            *(uint4*)(st + 3 * TILE_BYTES + so1) = rg[7];
            __syncthreads();
        }
    }
}

// ---------------------------------------------------------------------------
// Kernel 1: qkv (unchanged, measured 470us)
// ---------------------------------------------------------------------------
__global__ __launch_bounds__(512) void qkv_gemm() {
    extern __shared__ char smem[];
    const int m0 = blockIdx.y * 128;
    const int n0 = blockIdx.x * 128;
    float acc[2][4][4] = {};
    gemm_mainloop(g_xh, g_xl, g_wqh, g_wql, m0, n0, smem, acc);

    const int tid = threadIdx.x;
    const int lane = tid & 31;
    const int wid = tid >> 5;
    const int wm = wid & 3, wn = wid >> 2;
    const int t = n0 >> 10;               // 0=q,1=k,2=v

#pragma unroll
    for (int mf = 0; mf < 2; ++mf) {
        const int row = m0 + wm * 32 + mf * 16 + (lane >> 2);
#pragma unroll
        for (int nf = 0; nf < 4; ++nf) {
            const int col = n0 + wn * 32 + nf * 8 + ((lane & 3) << 1);
            const int h = (col >> 6) & 15;
            const int d = col & 63;
#pragma unroll
            for (int rr = 0; rr < 2; ++rr) {
                const int m = row + rr * 8;
                const int b = m >> 11, nr = m & 2047;
                const float v0 = acc[mf][nf][rr * 2 + 0];
                const float v1 = acc[mf][nf][rr * 2 + 1];
                uint32_t hp, lp;
                split2(v0, v1, hp, lp);
                if (t == 2) {
                    const size_t base = ((size_t)(b * H_ + h) * D_ + d) * N_ + nr;
                    __nv_bfloat162 hv = *reinterpret_cast<__nv_bfloat162*>(&hp);
                    __nv_bfloat162 lv = *reinterpret_cast<__nv_bfloat162*>(&lp);
                    g_vh[base] = hv.x; g_vh[base + N_] = hv.y;
                    g_vl[base] = lv.x; g_vl[base + N_] = lv.y;
                } else {
                    const size_t base = ((size_t)(b * H_ + h) * N_ + nr) * D_ + d;
                    __nv_bfloat16* dh = (t == 0) ? g_qh : g_kh;
                    __nv_bfloat16* dl = (t == 0) ? g_ql : g_kl;
                    *(uint32_t*)&dh[base] = hp;
                    *(uint32_t*)&dl[base] = lp;
                }
            }
        }
    }
}

// ---------------------------------------------------------------------------
// Kernel 3: proj (unchanged)
// ---------------------------------------------------------------------------
__global__ __launch_bounds__(512) void proj_gemm(const float* __restrict__ bias,
                                                 float* __restrict__ out) {
    extern __shared__ char smem[];
    const int m0 = blockIdx.y * 128;
    const int n0 = blockIdx.x * 128;
    float acc[2][4][4] = {};
    gemm_mainloop(g_ah, g_al, g_wph, g_wpl, m0, n0, smem, acc);

    const int tid = threadIdx.x;
    const int lane = tid & 31;
    const int wid = tid >> 5;
    const int wm = wid & 3, wn = wid >> 2;

#pragma unroll
    for (int mf = 0; mf < 2; ++mf) {
        const int row = m0 + wm * 32 + mf * 16 + (lane >> 2);
#pragma unroll
        for (int nf = 0; nf < 4; ++nf) {
            const int col = n0 + wn * 32 + nf * 8 + ((lane & 3) << 1);
            const float2 bv = *(const float2*)&bias[col];
            *(float2*)&out[(size_t)row * C_ + col] =
                make_float2(acc[mf][nf][0] + bv.x, acc[mf][nf][1] + bv.y);
            *(float2*)&out[(size_t)(row + 8) * C_ + col] =
                make_float2(acc[mf][nf][2] + bv.x, acc[mf][nf][3] + bv.y);
        }
    }
}

// ===========================================================================
// Kernel 2: FA2-style flash attention. 256 thr = 8 warps; warp owns m16 rows
// x full n64 KV strip. S stays in C-frag registers; softmax via shfl_xor over
// the 4 lanes per row; C-frag -> A-frag register identity feeds PV directly.
// Q A-frags in registers (loaded once). Smem = K/V hi/lo only (32KB) -> 2 CTAs.
// ===========================================================================
#define ZKH 0
#define ZKL 8192
#define ZVH 16384
#define ZVL 24576
#define ATTN_SMEM 32768

__global__ __launch_bounds__(256, 2) void attn_mma() {
    extern __shared__ char sm[];
    const uint32_t sb = smem_to_u32(sm);
    const int tid = threadIdx.x;
    const int lane = tid & 31;
    const int w = tid >> 5;              // 0..7, warp owns rows w*16..+15
    const int q0 = blockIdx.x * 128;
    const int bh = blockIdx.y;
    const int b = bh >> 4, h = bh & 15;

    const __nv_bfloat16* qhp = g_qh + (size_t)bh * N_ * D_;
    const __nv_bfloat16* qlp = g_ql + (size_t)bh * N_ * D_;
    const __nv_bfloat16* khp = g_kh + (size_t)bh * N_ * D_;
    const __nv_bfloat16* klp = g_kl + (size_t)bh * N_ * D_;
    const __nv_bfloat16* vhp = g_vh + (size_t)bh * D_ * N_;   // [D][N]
    const __nv_bfloat16* vlp = g_vl + (size_t)bh * D_ * N_;

    // Q A-frags in registers: a0=[r,k0-7] a1=[r+8,k0-7] a2=[r,k8-15] a3=[r+8,k8-15]
    uint32_t qfh[4][4], qfl[4][4];
    {
        const int r0 = q0 + w * 16 + (lane >> 2);
        const int k0 = (lane & 3) << 1;
#pragma unroll
        for (int ks = 0; ks < 4; ++ks) {
            const size_t base = (size_t)r0 * D_ + ks * 16 + k0;
            qfh[ks][0] = *(const uint32_t*)&qhp[base];
            qfh[ks][1] = *(const uint32_t*)&qhp[base + 8 * D_];
            qfh[ks][2] = *(const uint32_t*)&qhp[base + 8];
            qfh[ks][3] = *(const uint32_t*)&qhp[base + 8 * D_ + 8];
            qfl[ks][0] = *(const uint32_t*)&qlp[base];
            qfl[ks][1] = *(const uint32_t*)&qlp[base + 8 * D_];
            qfl[ks][2] = *(const uint32_t*)&qlp[base + 8];
            qfl[ks][3] = *(const uint32_t*)&qlp[base + 8 * D_ + 8];
        }
    }

    float acco[8][4] = {};
    float m0 = -1e30f, m1 = -1e30f, l0 = 0.0f, l1 = 0.0f;

    for (int c0 = 0; c0 < N_; c0 += 64) {
        __syncthreads();   // protect K/V reuse
        // load K tile [64 kv][64 k] and Vt tile [64 d][64 kv], hi/lo, swizzled
        {
            const int trow = tid >> 2;          // 0..63
            const int tch = (tid & 3) << 1;     // 0,2,4,6
            const uint32_t s0 = trow * 128 + (((tch + 0) ^ (trow & 7)) << 4);
            const uint32_t s1 = trow * 128 + (((tch + 1) ^ (trow & 7)) << 4);
            const uint4* ph = (const uint4*)(khp + (size_t)(c0 + trow) * D_) + tch;
            const uint4* pl = (const uint4*)(klp + (size_t)(c0 + trow) * D_) + tch;
            *(uint4*)(sm + ZKH + s0) = ph[0];
            *(uint4*)(sm + ZKH + s1) = ph[1];
            *(uint4*)(sm + ZKL + s0) = pl[0];
            *(uint4*)(sm + ZKL + s1) = pl[1];
            const uint4* pvh = (const uint4*)(vhp + (size_t)trow * N_ + c0) + tch;
            const uint4* pvl = (const uint4*)(vlp + (size_t)trow * N_ + c0) + tch;
            *(uint4*)(sm + ZVH + s0) = pvh[0];
            *(uint4*)(sm + ZVH + s1) = pvh[1];
            *(uint4*)(sm + ZVL + s0) = pvl[0];
            *(uint4*)(sm + ZVL + s1) = pvl[1];
        }
        __syncthreads();

        // S = Q @ K^T : 8 n8-blocks over kv
        float accs[8][4] = {};
#pragma unroll
        for (int ks = 0; ks < 4; ++ks) {
#pragma unroll
            for (int j = 0; j < 8; ++j) {
                const int row = j * 8 + (lane & 7);
                const int ch = ks * 2 + ((lane >> 3) & 1);
                const uint32_t off = row * 128 + ((ch ^ (row & 7)) << 4);
                uint32_t bhf[2], blf[2];
                ldsm_x2(bhf, sb + ZKH + off);
                ldsm_x2(blf, sb + ZKL + off);
                mma16816(accs[j], qfh[ks], bhf);
                mma16816(accs[j], qfh[ks], blf);
                mma16816(accs[j], qfl[ks], bhf);
            }
        }

        // register softmax; rows r0 = w*16+(lane>>2), r1 = r0+8
        float mx0 = -1e30f, mx1 = -1e30f;
#pragma unroll
        for (int j = 0; j < 8; ++j) {
            accs[j][0] *= 0.125f; accs[j][1] *= 0.125f;
            accs[j][2] *= 0.125f; accs[j][3] *= 0.125f;
            mx0 = fmaxf(mx0, fmaxf(accs[j][0], accs[j][1]));
            mx1 = fmaxf(mx1, fmaxf(accs[j][2], accs[j][3]));
        }
        mx0 = fmaxf(mx0, __shfl_xor_sync(0xffffffffu, mx0, 1));
        mx0 = fmaxf(mx0, __shfl_xor_sync(0xffffffffu, mx0, 2));
        mx1 = fmaxf(mx1, __shfl_xor_sync(0xffffffffu, mx1, 1));
        mx1 = fmaxf(mx1, __shfl_xor_sync(0xffffffffu, mx1, 2));
        mx0 = fmaxf(mx0, m0);
        mx1 = fmaxf(mx1, m1);
        const float al0 = __expf(m0 - mx0);
        const float al1 = __expf(m1 - mx1);
        m0 = mx0; m1 = mx1;

        float s0 = 0.0f, s1 = 0.0f;
        uint32_t ph[4][4], pl[4][4];   // P A-frags (C->A identity)
#pragma unroll
        for (int t = 0; t < 4; ++t) {
            const float p00 = __expf(accs[2 * t][0] - mx0);
            const float p01 = __expf(accs[2 * t][1] - mx0);
            const float p02 = __expf(accs[2 * t][2] - mx1);
            const float p03 = __expf(accs[2 * t][3] - mx1);
            const float p10 = __expf(accs[2 * t + 1][0] - mx0);
            const float p11 = __expf(accs[2 * t + 1][1] - mx0);
            const float p12 = __expf(accs[2 * t + 1][2] - mx1);
            const float p13 = __expf(accs[2 * t + 1][3] - mx1);
            s0 += (p00 + p01) + (p10 + p11);
            s1 += (p02 + p03) + (p12 + p13);
            split2(p00, p01, ph[t][0], pl[t][0]);   // a0: row r0, k0-7
            split2(p02, p03, ph[t][1], pl[t][1]);   // a1: row r1, k0-7
            split2(p10, p11, ph[t][2], pl[t][2]);   // a2: row r0, k8-15
            split2(p12, p13, ph[t][3], pl[t][3]);   // a3: row r1, k8-15
        }
        s0 += __shfl_xor_sync(0xffffffffu, s0, 1);
        s0 += __shfl_xor_sync(0xffffffffu, s0, 2);
        s1 += __shfl_xor_sync(0xffffffffu, s1, 1);
        s1 += __shfl_xor_sync(0xffffffffu, s1, 2);
        l0 = l0 * al0 + s0;
        l1 = l1 * al1 + s1;

        // rescale O, then O += P @ V
#pragma unroll
        for (int j = 0; j < 8; ++j) {
            acco[j][0] *= al0; acco[j][1] *= al0;
            acco[j][2] *= al1; acco[j][3] *= al1;
        }
#pragma unroll
        for (int t = 0; t < 4; ++t) {
#pragma unroll
            for (int j = 0; j < 8; ++j) {
                const int row = j * 8 + (lane & 7);          // d row of Vt
                const int ch = t * 2 + ((lane >> 3) & 1);    // kv chunk
                const uint32_t off = row * 128 + ((ch ^ (row & 7)) << 4);
                uint32_t vhf[2], vlf[2];
                ldsm_x2(vhf, sb + ZVH + off);
                ldsm_x2(vlf, sb + ZVL + off);
                mma16816(acco[j], ph[t], vhf);
                mma16816(acco[j], ph[t], vlf);
                mma16816(acco[j], pl[t], vhf);
            }
        }
    }

    // epilogue: O / l -> split-bf16 g_ah/g_al at [b][token][h*64 + d]
    const float i0 = 1.0f / l0;
    const float i1 = 1.0f / l1;
    const int r0 = q0 + w * 16 + (lane >> 2);
#pragma unroll
    for (int j = 0; j < 8; ++j) {
        const int d = j * 8 + ((lane & 3) << 1);
        uint32_t hp, lp;
        {
            const size_t base = (size_t)(b * N_ + r0) * C_ + (h << 6) + d;
            split2(acco[j][0] * i0, acco[j][1] * i0, hp, lp);
            *(uint32_t*)&g_ah[base] = hp;
            *(uint32_t*)&g_al[base] = lp;
        }
        {
            const size_t base = (size_t)(b * N_ + r0 + 8) * C_ + (h << 6) + d;
            split2(acco[j][2] * i1, acco[j][3] * i1, hp, lp);
            *(uint32_t*)&g_ah[base] = hp;
            *(uint32_t*)&g_al[base] = lp;
        }
    }
}

// ---------------------------------------------------------------------------
extern "C" void kernel_launch(void* const* d_in, const int* in_sizes, int n_in,
                              void* d_out, int out_size) {
    const float* x     = (const float*)d_in[0];   // [4,2048,1024]
    const float* Wqkv  = (const float*)d_in[1];   // [3072,1024]
    const float* Wproj = (const float*)d_in[2];   // [1024,1024]
    const float* bproj = (const float*)d_in[3];   // [1024]
    float* out = (float*)d_out;                   // [4,2048,1024]

    cudaFuncSetAttribute(qkv_gemm,
                         cudaFuncAttributeMaxDynamicSharedMemorySize, GEMM_SMEM);
    cudaFuncSetAttribute(proj_gemm,
                         cudaFuncAttributeMaxDynamicSharedMemorySize, GEMM_SMEM);
    cudaFuncSetAttribute(attn_mma,
                         cudaFuncAttributeMaxDynamicSharedMemorySize, ATTN_SMEM);

    // 0) split fp32 inputs into bf16 hi/lo
    split_x<<<(B_ * N_ * C_ / 4 + 255) / 256, 256>>>(x);
    split_wq<<<(3 * C_ * C_ / 4 + 255) / 256, 256>>>(Wqkv);
    split_wp<<<(C_ * C_ / 4 + 255) / 256, 256>>>(Wproj);
    // 1) QKV projection
    qkv_gemm<<<dim3(3 * C_ / 128, (B_ * N_) / 128), 512, GEMM_SMEM>>>();
    // 2) FA2-style attention (register softmax, 2 CTAs/SM)
    attn_mma<<<dim3(N_ / 128, B_ * H_), 256, ATTN_SMEM>>>();
    // 3) Output projection + bias
    proj_gemm<<<dim3(C_ / 128, (B_ * N_) / 128), 512, GEMM_SMEM>>>(bproj, out);
}

// round 17
// speedup vs baseline: 2.7918x; 1.0429x over previous
#include <cuda_runtime.h>
#include <cuda_bf16.h>
#include <cstdint>

// Problem constants
#define B_ 4
#define N_ 2048
#define C_ 1024
#define H_ 16
#define D_ 64

// split-bf16 (hi/lo) buffers
__device__ __nv_bfloat16 g_xh[B_ * N_ * C_], g_xl[B_ * N_ * C_];
__device__ __nv_bfloat16 g_wqh[3 * C_ * C_], g_wql[3 * C_ * C_];
__device__ __nv_bfloat16 g_wph[C_ * C_], g_wpl[C_ * C_];
__device__ __nv_bfloat16 g_qh[B_ * H_ * N_ * D_], g_ql[B_ * H_ * N_ * D_];  // [B,H,N,D]
__device__ __nv_bfloat16 g_kh[B_ * H_ * N_ * D_], g_kl[B_ * H_ * N_ * D_];  // [B,H,N,D]
__device__ __nv_bfloat16 g_vh[B_ * H_ * N_ * D_], g_vl[B_ * H_ * N_ * D_];  // [B,H,D,N] (!)
__device__ __nv_bfloat16 g_ah[B_ * N_ * C_], g_al[B_ * N_ * C_];            // [B,N,C]

// ===========================================================================
// helpers
// ===========================================================================
__device__ __forceinline__ uint32_t smem_to_u32(const void* p) {
    uint32_t a;
    asm("{ .reg .u64 t; cvta.to.shared.u64 t, %1; cvt.u32.u64 %0, t; }"
        : "=r"(a) : "l"(p));
    return a;
}
__device__ __forceinline__ uint32_t bf2u(__nv_bfloat162 v) {
    return *reinterpret_cast<uint32_t*>(&v);
}
// split two floats -> (hi bf16x2, lo bf16x2)
__device__ __forceinline__ void split2(float x, float y, uint32_t& hi, uint32_t& lo) {
    __nv_bfloat162 h = __floats2bfloat162_rn(x, y);
    __nv_bfloat162 l = __floats2bfloat162_rn(x - __bfloat162float(h.x),
                                             y - __bfloat162float(h.y));
    hi = bf2u(h);
    lo = bf2u(l);
}

// mma.sync m16n8k16 bf16 (HW-validated)
__device__ __forceinline__ void mma16816(float* d, const uint32_t* a, const uint32_t* b) {
    asm volatile(
        "mma.sync.aligned.m16n8k16.row.col.f32.bf16.bf16.f32 "
        "{%0,%1,%2,%3},{%4,%5,%6,%7},{%8,%9},{%0,%1,%2,%3};"
        : "+f"(d[0]), "+f"(d[1]), "+f"(d[2]), "+f"(d[3])
        : "r"(a[0]), "r"(a[1]), "r"(a[2]), "r"(a[3]), "r"(b[0]), "r"(b[1]));
}
__device__ __forceinline__ void ldsm_x4(uint32_t* r, uint32_t addr) {
    asm volatile("ldmatrix.sync.aligned.m8n8.x4.shared.b16 {%0,%1,%2,%3}, [%4];"
                 : "=r"(r[0]), "=r"(r[1]), "=r"(r[2]), "=r"(r[3]) : "r"(addr));
}
__device__ __forceinline__ void ldsm_x2(uint32_t* r, uint32_t addr) {
    asm volatile("ldmatrix.sync.aligned.m8n8.x2.shared.b16 {%0,%1}, [%2];"
                 : "=r"(r[0]), "=r"(r[1]) : "r"(addr));
}
// cp.async 16B (sm_80+)
__device__ __forceinline__ void cp_async16(uint32_t dst, const void* src) {
    asm volatile("cp.async.cg.shared.global [%0], [%1], 16;" :: "r"(dst), "l"(src) : "memory");
}
#define CP_COMMIT() asm volatile("cp.async.commit_group;" ::: "memory")
#define CP_WAIT0()  asm volatile("cp.async.wait_group 0;" ::: "memory")

// ===========================================================================
// split kernels: fp32 -> bf16 hi + lo
// ===========================================================================
__device__ __forceinline__ void split_store(const float* __restrict__ s,
                                            __nv_bfloat16* hi, __nv_bfloat16* lo,
                                            int i) {
    float4 v = ((const float4*)s)[i];
    uint32_t h0, l0, h1, l1;
    split2(v.x, v.y, h0, l0);
    split2(v.z, v.w, h1, l1);
    ((uint2*)hi)[i] = make_uint2(h0, h1);
    ((uint2*)lo)[i] = make_uint2(l0, l1);
}
__global__ __launch_bounds__(256) void split_x(const float* __restrict__ s) {
    int i = blockIdx.x * blockDim.x + threadIdx.x;
    if (i < B_ * N_ * C_ / 4) split_store(s, g_xh, g_xl, i);
}
__global__ __launch_bounds__(256) void split_wq(const float* __restrict__ s) {
    int i = blockIdx.x * blockDim.x + threadIdx.x;
    if (i < 3 * C_ * C_ / 4) split_store(s, g_wqh, g_wql, i);
}
__global__ __launch_bounds__(256) void split_wp(const float* __restrict__ s) {
    int i = blockIdx.x * blockDim.x + threadIdx.x;
    if (i < C_ * C_ / 4) split_store(s, g_wph, g_wpl, i);
}

// ===========================================================================
// mma.sync GEMM mainloop with cp.async double-buffering.
// C[128x128] = A[128xK] * B[128xK]^T, K=1024, 512 thr = 16 warps 4x4.
// Per iter: wait_group 0 -> bar -> issue next-stage cp.async -> compute.
// ===========================================================================
#define TILE_BYTES 16384
#define STAGE_BYTES (4 * TILE_BYTES)
#define GEMM_SMEM (2 * STAGE_BYTES)   // 131072

__device__ __forceinline__ void gemm_mainloop(const __nv_bfloat16* __restrict__ Ah,
                                              const __nv_bfloat16* __restrict__ Al,
                                              const __nv_bfloat16* __restrict__ Bh,
                                              const __nv_bfloat16* __restrict__ Bl,
                                              int m0, int n0, char* smem,
                                              float acc[2][4][4]) {
    const int tid = threadIdx.x;
    const int lane = tid & 31;
    const int wid = tid >> 5;
    const int wm = wid & 3, wn = wid >> 2;

    const int grow = tid >> 2;
    const int gc = (tid & 3) << 1;
    const uint4* pAh = (const uint4*)(Ah + (size_t)(m0 + grow) * C_) + gc;
    const uint4* pAl = (const uint4*)(Al + (size_t)(m0 + grow) * C_) + gc;
    const uint4* pBh = (const uint4*)(Bh + (size_t)(n0 + grow) * C_) + gc;
    const uint4* pBl = (const uint4*)(Bl + (size_t)(n0 + grow) * C_) + gc;
    const uint32_t so0 = (uint32_t)(grow * 128 + (((gc + 0) ^ (grow & 7)) << 4));
    const uint32_t so1 = (uint32_t)(grow * 128 + (((gc + 1) ^ (grow & 7)) << 4));
    const uint32_t smem_u32 = smem_to_u32(smem);

    // prologue: stage 0 via cp.async
    {
        const uint32_t st = smem_u32;
        cp_async16(st + 0 * TILE_BYTES + so0, pAh + 0);
        cp_async16(st + 0 * TILE_BYTES + so1, pAh + 1);
        cp_async16(st + 1 * TILE_BYTES + so0, pAl + 0);
        cp_async16(st + 1 * TILE_BYTES + so1, pAl + 1);
        cp_async16(st + 2 * TILE_BYTES + so0, pBh + 0);
        cp_async16(st + 2 * TILE_BYTES + so1, pBh + 1);
        cp_async16(st + 3 * TILE_BYTES + so0, pBl + 0);
        cp_async16(st + 3 * TILE_BYTES + so1, pBl + 1);
        CP_COMMIT();
    }

    for (int it = 0; it < 16; ++it) {
        CP_WAIT0();
        __syncthreads();   // stage it fully visible; prior reads of next buffer done
        if (it + 1 < 16) {
            const int o = (it + 1) * 8;
            const uint32_t st = smem_u32 + ((it + 1) & 1) * STAGE_BYTES;
            cp_async16(st + 0 * TILE_BYTES + so0, pAh + o);
            cp_async16(st + 0 * TILE_BYTES + so1, pAh + o + 1);
            cp_async16(st + 1 * TILE_BYTES + so0, pAl + o);
            cp_async16(st + 1 * TILE_BYTES + so1, pAl + o + 1);
            cp_async16(st + 2 * TILE_BYTES + so0, pBh + o);
            cp_async16(st + 2 * TILE_BYTES + so1, pBh + o + 1);
            cp_async16(st + 3 * TILE_BYTES + so0, pBl + o);
            cp_async16(st + 3 * TILE_BYTES + so1, pBl + o + 1);
            CP_COMMIT();
        }
        const uint32_t sb = smem_u32 + (it & 1) * STAGE_BYTES;
#pragma unroll
        for (int ks = 0; ks < 4; ++ks) {
            uint32_t ahf[2][4], alf[2][4];
#pragma unroll
            for (int mf = 0; mf < 2; ++mf) {
                const int row = wm * 32 + mf * 16 + (lane & 15);
                const int ch = ks * 2 + (lane >> 4);
                const uint32_t off = row * 128 + ((ch ^ (row & 7)) << 4);
                ldsm_x4(ahf[mf], sb + 0 * TILE_BYTES + off);
                ldsm_x4(alf[mf], sb + 1 * TILE_BYTES + off);
            }
#pragma unroll
            for (int nf = 0; nf < 4; ++nf) {
                const int row = wn * 32 + nf * 8 + (lane & 7);
                const int ch = ks * 2 + ((lane >> 3) & 1);
                const uint32_t off = row * 128 + ((ch ^ (row & 7)) << 4);
                uint32_t bhf[2], blf[2];
                ldsm_x2(bhf, sb + 2 * TILE_BYTES + off);
                ldsm_x2(blf, sb + 3 * TILE_BYTES + off);
#pragma unroll
                for (int mf = 0; mf < 2; ++mf) {
                    mma16816(acc[mf][nf], ahf[mf], bhf);
                    mma16816(acc[mf][nf], ahf[mf], blf);
                    mma16816(acc[mf][nf], alf[mf], bhf);
                }
            }
        }
    }
}

// ---------------------------------------------------------------------------
// Kernel 1: qkv = x @ W_qkv^T -> split-bf16 q/k ([B,H,N,D]) and v ([B,H,D,N])
// ---------------------------------------------------------------------------
__global__ __launch_bounds__(512) void qkv_gemm() {
    extern __shared__ char smem[];
    const int m0 = blockIdx.y * 128;
    const int n0 = blockIdx.x * 128;
    float acc[2][4][4] = {};
    gemm_mainloop(g_xh, g_xl, g_wqh, g_wql, m0, n0, smem, acc);

    const int tid = threadIdx.x;
    const int lane = tid & 31;
    const int wid = tid >> 5;
    const int wm = wid & 3, wn = wid >> 2;
    const int t = n0 >> 10;               // 0=q,1=k,2=v

#pragma unroll
    for (int mf = 0; mf < 2; ++mf) {
        const int row = m0 + wm * 32 + mf * 16 + (lane >> 2);
#pragma unroll
        for (int nf = 0; nf < 4; ++nf) {
            const int col = n0 + wn * 32 + nf * 8 + ((lane & 3) << 1);
            const int h = (col >> 6) & 15;
            const int d = col & 63;
#pragma unroll
            for (int rr = 0; rr < 2; ++rr) {
                const int m = row + rr * 8;
                const int b = m >> 11, nr = m & 2047;
                const float v0 = acc[mf][nf][rr * 2 + 0];
                const float v1 = acc[mf][nf][rr * 2 + 1];
                uint32_t hp, lp;
                split2(v0, v1, hp, lp);
                if (t == 2) {
                    const size_t base = ((size_t)(b * H_ + h) * D_ + d) * N_ + nr;
                    __nv_bfloat162 hv = *reinterpret_cast<__nv_bfloat162*>(&hp);
                    __nv_bfloat162 lv = *reinterpret_cast<__nv_bfloat162*>(&lp);
                    g_vh[base] = hv.x; g_vh[base + N_] = hv.y;
                    g_vl[base] = lv.x; g_vl[base + N_] = lv.y;
                } else {
                    const size_t base = ((size_t)(b * H_ + h) * N_ + nr) * D_ + d;
                    __nv_bfloat16* dh = (t == 0) ? g_qh : g_kh;
                    __nv_bfloat16* dl = (t == 0) ? g_ql : g_kl;
                    *(uint32_t*)&dh[base] = hp;
                    *(uint32_t*)&dl[base] = lp;
                }
            }
        }
    }
}

// ---------------------------------------------------------------------------
// Kernel 3: out = attn @ W_proj^T + b_proj
// ---------------------------------------------------------------------------
__global__ __launch_bounds__(512) void proj_gemm(const float* __restrict__ bias,
                                                 float* __restrict__ out) {
    extern __shared__ char smem[];
    const int m0 = blockIdx.y * 128;
    const int n0 = blockIdx.x * 128;
    float acc[2][4][4] = {};
    gemm_mainloop(g_ah, g_al, g_wph, g_wpl, m0, n0, smem, acc);

    const int tid = threadIdx.x;
    const int lane = tid & 31;
    const int wid = tid >> 5;
    const int wm = wid & 3, wn = wid >> 2;

#pragma unroll
    for (int mf = 0; mf < 2; ++mf) {
        const int row = m0 + wm * 32 + mf * 16 + (lane >> 2);
#pragma unroll
        for (int nf = 0; nf < 4; ++nf) {
            const int col = n0 + wn * 32 + nf * 8 + ((lane & 3) << 1);
            const float2 bv = *(const float2*)&bias[col];
            *(float2*)&out[(size_t)row * C_ + col] =
                make_float2(acc[mf][nf][0] + bv.x, acc[mf][nf][1] + bv.y);
            *(float2*)&out[(size_t)(row + 8) * C_ + col] =
                make_float2(acc[mf][nf][2] + bv.x, acc[mf][nf][3] + bv.y);
        }
    }
}

// ===========================================================================
// Kernel 2: FA2-style flash attention (R16 winner, unchanged).
// 256 thr = 8 warps; warp owns m16 x n64 strip; register softmax; 2 CTAs/SM.
// ===========================================================================
#define ZKH 0
#define ZKL 8192
#define ZVH 16384
#define ZVL 24576
#define ATTN_SMEM 32768

__global__ __launch_bounds__(256, 2) void attn_mma() {
    extern __shared__ char sm[];
    const uint32_t sb = smem_to_u32(sm);
    const int tid = threadIdx.x;
    const int lane = tid & 31;
    const int w = tid >> 5;
    const int q0 = blockIdx.x * 128;
    const int bh = blockIdx.y;
    const int b = bh >> 4, h = bh & 15;

    const __nv_bfloat16* qhp = g_qh + (size_t)bh * N_ * D_;
    const __nv_bfloat16* qlp = g_ql + (size_t)bh * N_ * D_;
    const __nv_bfloat16* khp = g_kh + (size_t)bh * N_ * D_;
    const __nv_bfloat16* klp = g_kl + (size_t)bh * N_ * D_;
    const __nv_bfloat16* vhp = g_vh + (size_t)bh * D_ * N_;   // [D][N]
    const __nv_bfloat16* vlp = g_vl + (size_t)bh * D_ * N_;

    uint32_t qfh[4][4], qfl[4][4];
    {
        const int r0 = q0 + w * 16 + (lane >> 2);
        const int k0 = (lane & 3) << 1;
#pragma unroll
        for (int ks = 0; ks < 4; ++ks) {
            const size_t base = (size_t)r0 * D_ + ks * 16 + k0;
            qfh[ks][0] = *(const uint32_t*)&qhp[base];
            qfh[ks][1] = *(const uint32_t*)&qhp[base + 8 * D_];
            qfh[ks][2] = *(const uint32_t*)&qhp[base + 8];
            qfh[ks][3] = *(const uint32_t*)&qhp[base + 8 * D_ + 8];
            qfl[ks][0] = *(const uint32_t*)&qlp[base];
            qfl[ks][1] = *(const uint32_t*)&qlp[base + 8 * D_];
            qfl[ks][2] = *(const uint32_t*)&qlp[base + 8];
            qfl[ks][3] = *(const uint32_t*)&qlp[base + 8 * D_ + 8];
        }
    }

    float acco[8][4] = {};
    float m0 = -1e30f, m1 = -1e30f, l0 = 0.0f, l1 = 0.0f;

    for (int c0 = 0; c0 < N_; c0 += 64) {
        __syncthreads();
        {
            const int trow = tid >> 2;
            const int tch = (tid & 3) << 1;
            const uint32_t s0 = trow * 128 + (((tch + 0) ^ (trow & 7)) << 4);
            const uint32_t s1 = trow * 128 + (((tch + 1) ^ (trow & 7)) << 4);
            const uint4* ph = (const uint4*)(khp + (size_t)(c0 + trow) * D_) + tch;
            const uint4* pl = (const uint4*)(klp + (size_t)(c0 + trow) * D_) + tch;
            *(uint4*)(sm + ZKH + s0) = ph[0];
            *(uint4*)(sm + ZKH + s1) = ph[1];
            *(uint4*)(sm + ZKL + s0) = pl[0];
            *(uint4*)(sm + ZKL + s1) = pl[1];
            const uint4* pvh = (const uint4*)(vhp + (size_t)trow * N_ + c0) + tch;
            const uint4* pvl = (const uint4*)(vlp + (size_t)trow * N_ + c0) + tch;
            *(uint4*)(sm + ZVH + s0) = pvh[0];
            *(uint4*)(sm + ZVH + s1) = pvh[1];
            *(uint4*)(sm + ZVL + s0) = pvl[0];
            *(uint4*)(sm + ZVL + s1) = pvl[1];
        }
        __syncthreads();

        float accs[8][4] = {};
#pragma unroll
        for (int ks = 0; ks < 4; ++ks) {
#pragma unroll
            for (int j = 0; j < 8; ++j) {
                const int row = j * 8 + (lane & 7);
                const int ch = ks * 2 + ((lane >> 3) & 1);
                const uint32_t off = row * 128 + ((ch ^ (row & 7)) << 4);
                uint32_t bhf[2], blf[2];
                ldsm_x2(bhf, sb + ZKH + off);
                ldsm_x2(blf, sb + ZKL + off);
                mma16816(accs[j], qfh[ks], bhf);
                mma16816(accs[j], qfh[ks], blf);
                mma16816(accs[j], qfl[ks], bhf);
            }
        }

        float mx0 = -1e30f, mx1 = -1e30f;
#pragma unroll
        for (int j = 0; j < 8; ++j) {
            accs[j][0] *= 0.125f; accs[j][1] *= 0.125f;
            accs[j][2] *= 0.125f; accs[j][3] *= 0.125f;
            mx0 = fmaxf(mx0, fmaxf(accs[j][0], accs[j][1]));
            mx1 = fmaxf(mx1, fmaxf(accs[j][2], accs[j][3]));
        }
        mx0 = fmaxf(mx0, __shfl_xor_sync(0xffffffffu, mx0, 1));
        mx0 = fmaxf(mx0, __shfl_xor_sync(0xffffffffu, mx0, 2));
        mx1 = fmaxf(mx1, __shfl_xor_sync(0xffffffffu, mx1, 1));
        mx1 = fmaxf(mx1, __shfl_xor_sync(0xffffffffu, mx1, 2));
        mx0 = fmaxf(mx0, m0);
        mx1 = fmaxf(mx1, m1);
        const float al0 = __expf(m0 - mx0);
        const float al1 = __expf(m1 - mx1);
        m0 = mx0; m1 = mx1;

        float s0 = 0.0f, s1 = 0.0f;
        uint32_t ph[4][4], pl[4][4];
#pragma unroll
        for (int t = 0; t < 4; ++t) {
            const float p00 = __expf(accs[2 * t][0] - mx0);
            const float p01 = __expf(accs[2 * t][1] - mx0);
            const float p02 = __expf(accs[2 * t][2] - mx1);
            const float p03 = __expf(accs[2 * t][3] - mx1);
            const float p10 = __expf(accs[2 * t + 1][0] - mx0);
            const float p11 = __expf(accs[2 * t + 1][1] - mx0);
            const float p12 = __expf(accs[2 * t + 1][2] - mx1);
            const float p13 = __expf(accs[2 * t + 1][3] - mx1);
            s0 += (p00 + p01) + (p10 + p11);
            s1 += (p02 + p03) + (p12 + p13);
            split2(p00, p01, ph[t][0], pl[t][0]);
            split2(p02, p03, ph[t][1], pl[t][1]);
            split2(p10, p11, ph[t][2], pl[t][2]);
            split2(p12, p13, ph[t][3], pl[t][3]);
        }
        s0 += __shfl_xor_sync(0xffffffffu, s0, 1);
        s0 += __shfl_xor_sync(0xffffffffu, s0, 2);
        s1 += __shfl_xor_sync(0xffffffffu, s1, 1);
        s1 += __shfl_xor_sync(0xffffffffu, s1, 2);
        l0 = l0 * al0 + s0;
        l1 = l1 * al1 + s1;

#pragma unroll
        for (int j = 0; j < 8; ++j) {
            acco[j][0] *= al0; acco[j][1] *= al0;
            acco[j][2] *= al1; acco[j][3] *= al1;
        }
#pragma unroll
        for (int t = 0; t < 4; ++t) {
#pragma unroll
            for (int j = 0; j < 8; ++j) {
                const int row = j * 8 + (lane & 7);
                const int ch = t * 2 + ((lane >> 3) & 1);
                const uint32_t off = row * 128 + ((ch ^ (row & 7)) << 4);
                uint32_t vhf[2], vlf[2];
                ldsm_x2(vhf, sb + ZVH + off);
                ldsm_x2(vlf, sb + ZVL + off);
                mma16816(acco[j], ph[t], vhf);
                mma16816(acco[j], ph[t], vlf);
                mma16816(acco[j], pl[t], vhf);
            }
        }
    }

    const float i0 = 1.0f / l0;
    const float i1 = 1.0f / l1;
    const int r0 = q0 + w * 16 + (lane >> 2);
#pragma unroll
    for (int j = 0; j < 8; ++j) {
        const int d = j * 8 + ((lane & 3) << 1);
        uint32_t hp, lp;
        {
            const size_t base = (size_t)(b * N_ + r0) * C_ + (h << 6) + d;
            split2(acco[j][0] * i0, acco[j][1] * i0, hp, lp);
            *(uint32_t*)&g_ah[base] = hp;
            *(uint32_t*)&g_al[base] = lp;
        }
        {
            const size_t base = (size_t)(b * N_ + r0 + 8) * C_ + (h << 6) + d;
            split2(acco[j][2] * i1, acco[j][3] * i1, hp, lp);
            *(uint32_t*)&g_ah[base] = hp;
            *(uint32_t*)&g_al[base] = lp;
        }
    }
}

// ---------------------------------------------------------------------------
extern "C" void kernel_launch(void* const* d_in, const int* in_sizes, int n_in,
                              void* d_out, int out_size) {
    const float* x     = (const float*)d_in[0];   // [4,2048,1024]
    const float* Wqkv  = (const float*)d_in[1];   // [3072,1024]
    const float* Wproj = (const float*)d_in[2];   // [1024,1024]
    const float* bproj = (const float*)d_in[3];   // [1024]
    float* out = (float*)d_out;                   // [4,2048,1024]

    cudaFuncSetAttribute(qkv_gemm,
                         cudaFuncAttributeMaxDynamicSharedMemorySize, GEMM_SMEM);
    cudaFuncSetAttribute(proj_gemm,
                         cudaFuncAttributeMaxDynamicSharedMemorySize, GEMM_SMEM);
    cudaFuncSetAttribute(attn_mma,
                         cudaFuncAttributeMaxDynamicSharedMemorySize, ATTN_SMEM);

    // 0) split fp32 inputs into bf16 hi/lo
    split_x<<<(B_ * N_ * C_ / 4 + 255) / 256, 256>>>(x);
    split_wq<<<(3 * C_ * C_ / 4 + 255) / 256, 256>>>(Wqkv);
    split_wp<<<(C_ * C_ / 4 + 255) / 256, 256>>>(Wproj);
    // 1) QKV projection (cp.async pipelined GEMM)
    qkv_gemm<<<dim3(3 * C_ / 128, (B_ * N_) / 128), 512, GEMM_SMEM>>>();
    // 2) FA2-style attention
    attn_mma<<<dim3(N_ / 128, B_ * H_), 256, ATTN_SMEM>>>();
    // 3) Output projection + bias (cp.async pipelined GEMM)
    proj_gemm<<<dim3(C_ / 128, (B_ * N_) / 128), 512, GEMM_SMEM>>>(bproj, out);
}